// round 10
// baseline (speedup 1.0000x reference)
#include <cuda_runtime.h>
#include <cstdint>

#define NN 50000      // nodes
#define NE 800000     // edges
#define NP 50048      // nodes padded to multiple of 128
#define NB 98         // scan blocks: ceil(NP/512)
#define ED 64         // edge feature dim
#define HID 152

// ---------------- scratch (device globals; no allocation allowed) ----------
__device__ int   g_cnt[NP];
__device__ int   g_fill[NP];
__device__ int   g_base[NP + 1];
__device__ int   g_bsum[128];
__device__ int   g_src[NE];      // src node per edge, CSR-ordered by dst
__device__ int   g_eid[NE];      // original edge id, CSR-ordered by dst
__device__ float g_eagg[(size_t)NP * ED];
__device__ float g_h1[(size_t)NP * HID];
__device__ float g_h2[(size_t)NP * HID];
__device__ float g_xc1[(size_t)NP * 208];
__device__ float g_xc2[(size_t)NP * 384];
__device__ float g_wc1[192 * 208];
__device__ float g_wc2[192 * 384];
__device__ float g_wc3[64 * 384];

// ---------------- utility ---------------------------------------------------
__global__ void k_zero_f(float* __restrict__ p, int n) {
    int t = blockIdx.x * blockDim.x + threadIdx.x;
    if (t < n) p[t] = 0.f;
}
__global__ void k_zero_i(int* __restrict__ p, int n) {
    int t = blockIdx.x * blockDim.x + threadIdx.x;
    if (t < n) p[t] = 0;
}

// ---------------- CSR build -------------------------------------------------
__global__ void k_count(const int* __restrict__ dst) {
    int t = blockIdx.x * blockDim.x + threadIdx.x;
    if (t < NE) atomicAdd(&g_cnt[dst[t]], 1);
}

__global__ void k_scan1() {
    __shared__ int sh[512];
    int b = blockIdx.x, t = threadIdx.x, i = b * 512 + t;
    int v = (i < NP) ? g_cnt[i] : 0;
    sh[t] = v;
    __syncthreads();
#pragma unroll
    for (int o = 1; o < 512; o <<= 1) {
        int x = (t >= o) ? sh[t - o] : 0;
        __syncthreads();
        sh[t] += x;
        __syncthreads();
    }
    if (i < NP) g_base[i + 1] = sh[t];
    if (t == 511) g_bsum[b] = sh[511];
}

__global__ void k_scan2() {
    if (threadIdx.x == 0) {
        int s = 0;
        for (int b = 0; b < NB; b++) { int c = g_bsum[b]; g_bsum[b] = s; s += c; }
    }
}

__global__ void k_scan3() {
    int i = blockIdx.x * blockDim.x + threadIdx.x;
    if (i < NP) g_base[i + 1] += g_bsum[i >> 9];
    if (i == 0) g_base[0] = 0;
}

__global__ void k_fill(const int* __restrict__ src, const int* __restrict__ dst) {
    int t = blockIdx.x * blockDim.x + threadIdx.x;
    if (t >= NE) return;
    int d = dst[t];
    int p = g_base[d] + atomicAdd(&g_fill[d], 1);
    g_src[p] = src[t];
    g_eid[p] = t;
}

// ---------------- edge-feature gather-sum per dst node ----------------------
__global__ void k_gather_e(const float* __restrict__ ef) {
    int w = (blockIdx.x * blockDim.x + threadIdx.x) >> 5;
    int lane = threadIdx.x & 31;
    if (w >= NN || lane >= 16) return;
    int e0 = g_base[w], e1 = g_base[w + 1];
    float4 a = {0.f, 0.f, 0.f, 0.f};
    for (int e = e0; e < e1; e++) {
        int id = g_eid[e];
        float4 v = *(const float4*)(ef + (size_t)id * ED + lane * 4);
        a.x += v.x; a.y += v.y; a.z += v.z; a.w += v.w;
    }
    *(float4*)(g_eagg + (size_t)w * ED + lane * 4) = a;
}

// ---------------- static columns of fused GEMM input (once per launch) ------
// layout per row v: [0,FIN)=x  [FIN,2FIN)=inv*na  [2FIN,2FIN+64)=inv*eagg
//                   [2FIN+64]=indicator  rest=0 ; pad rows fully 0
template <int KP, int FIN>
__global__ void k_static(float* __restrict__ XC) {
    int t = blockIdx.x * blockDim.x + threadIdx.x;
    if (t >= NP * KP) return;
    int v = t / KP, col = t - v * KP;
    float* p = XC + (size_t)v * KP + col;
    if (v >= NN) { *p = 0.f; return; }
    if (col < 2 * FIN) return;                 // dynamic: written by gather each layer
    int dg = g_cnt[v];
    float val = 0.f;
    if (col < 2 * FIN + 64) {
        float inv = 1.f / (float)max(dg, 1);
        val = inv * g_eagg[(size_t)v * ED + (col - 2 * FIN)];
    } else if (col == 2 * FIN + 64) {
        val = (dg > 0) ? 1.f : 0.f;
    }
    *p = val;
}

// ---------------- per-layer: copy x + gather mean of src rows into XC -------
template <int NC4, int FIN, int KP>
__global__ void k_gather(const float* __restrict__ X, int ldx, float* __restrict__ XC) {
    int w = (blockIdx.x * blockDim.x + threadIdx.x) >> 5;
    int lane = threadIdx.x & 31;
    if (w >= NN) return;
    int e0 = g_base[w], e1 = g_base[w + 1];
    int c0 = lane, c1 = lane + 32;
    float4 a0 = {0.f, 0.f, 0.f, 0.f};
    float4 a1 = {0.f, 0.f, 0.f, 0.f};
    for (int e = e0; e < e1; e++) {
        int s = g_src[e];
        const float4* row = (const float4*)(X + (size_t)s * ldx);
        if (c0 < NC4) {
            float4 v = row[c0];
            a0.x += v.x; a0.y += v.y; a0.z += v.z; a0.w += v.w;
        }
        if (NC4 > 32 && c1 < NC4) {
            float4 v = row[c1];
            a1.x += v.x; a1.y += v.y; a1.z += v.z; a1.w += v.w;
        }
    }
    float inv = 1.f / fmaxf((float)(e1 - e0), 1.f);
    float4* out = (float4*)(XC + (size_t)w * KP);
    const float4* xrow = (const float4*)(X + (size_t)w * ldx);
    if (c0 < NC4) {
        out[c0] = xrow[c0];
        float4 r; r.x = a0.x * inv; r.y = a0.y * inv; r.z = a0.z * inv; r.w = a0.w * inv;
        out[FIN / 4 + c0] = r;
    }
    if (NC4 > 32 && c1 < NC4) {
        out[c1] = xrow[c1];
        float4 r; r.x = a1.x * inv; r.y = a1.y * inv; r.z = a1.z * inv; r.w = a1.w * inv;
        out[FIN / 4 + c1] = r;
    }
}

// ---------------- build fused weight Wc = [Wa_self | Wa_h@Wm_n | Wa_h@Wm_e | Wa_h@bm]
__global__ void k_wc(const float* __restrict__ Wm, const float* __restrict__ bm,
                     const float* __restrict__ Wa, float* __restrict__ Wc,
                     int Fin, int Fm, int Fout, int Kp) {
    int col = blockIdx.x * blockDim.x + threadIdx.x;
    int j = blockIdx.y;
    int K1 = 2 * Fin + ED + 1;
    if (col >= K1 || j >= Fout) return;
    int WmK = Fin + ED;
    int WaK = Fin + Fm;
    const float* wah = Wa + (size_t)j * WaK + Fin;
    float val;
    if (col < Fin) {
        val = Wa[(size_t)j * WaK + col];
    } else if (col < 2 * Fin) {
        int i = col - Fin;
        float s = 0.f;
        for (int t = 0; t < Fm; t++) s += wah[t] * Wm[(size_t)t * WmK + i];
        val = s;
    } else if (col < 2 * Fin + ED) {
        int i = col - 2 * Fin;
        float s = 0.f;
        for (int t = 0; t < Fm; t++) s += wah[t] * Wm[(size_t)t * WmK + Fin + i];
        val = s;
    } else {
        float s = 0.f;
        for (int t = 0; t < Fm; t++) s += wah[t] * bm[t];
        val = s;
    }
    Wc[(size_t)j * Kp + col] = val;
}

// ---------------- tensor-core tf32x3 GEMM: C = relu(Xc @ Wc^T + bias) -------
// BM=128, BN=64, BK=16; 256 threads = 8 warps in 4(m) x 2(n); warp tile 32x32.
// hi/lo tf32 split done at TILE STAGING (amortized across warps); the inner
// loop is pure LDS + mma.sync.m16n8k8 (3-term: hi*hi + lo*hi + hi*lo).

__device__ __forceinline__ void split_tf32(float f, uint32_t& hi, uint32_t& lo) {
    asm("cvt.rna.tf32.f32 %0, %1;" : "=r"(hi) : "f"(f));
    float r = f - __uint_as_float(hi);
    asm("cvt.rna.tf32.f32 %0, %1;" : "=r"(lo) : "f"(r));
}

__device__ __forceinline__ void mma_tf32(float* c, const uint32_t* a, const uint32_t* b) {
    asm volatile(
        "mma.sync.aligned.m16n8k8.row.col.f32.tf32.tf32.f32 "
        "{%0,%1,%2,%3}, {%4,%5,%6,%7}, {%8,%9}, {%0,%1,%2,%3};"
        : "+f"(c[0]), "+f"(c[1]), "+f"(c[2]), "+f"(c[3])
        : "r"(a[0]), "r"(a[1]), "r"(a[2]), "r"(a[3]), "r"(b[0]), "r"(b[1]));
}

__global__ __launch_bounds__(256) void k_gemm_tc(
    const float* __restrict__ A, const float* __restrict__ B,
    const float* __restrict__ bias, float* __restrict__ C,
    int M, int Nout, int Kp, int ldc) {
    __shared__ uint32_t Ahi[16][136], Alo[16][136];   // [k][m] stride 136: frag loads conflict-free
    __shared__ uint32_t Bhi[64][20],  Blo[64][20];    // [n][k] stride 20:  frag loads conflict-free
    const int m0 = blockIdx.x * 128;
    const int n0 = blockIdx.y * 64;
    const int tid = threadIdx.x;
    const int lane = tid & 31, wid = tid >> 5;
    const int mw = wid >> 1, nw = wid & 1;     // 4 x 2 warp grid
    const int g = lane >> 2, t4 = lane & 3;

    float acc[2][4][4];
#pragma unroll
    for (int i = 0; i < 2; i++)
#pragma unroll
        for (int j = 0; j < 4; j++)
#pragma unroll
            for (int e = 0; e < 4; e++) acc[i][j][e] = 0.f;

    for (int k0 = 0; k0 < Kp; k0 += 16) {
        // stage A tile 128x16 (split to hi/lo at staging)
#pragma unroll
        for (int i = 0; i < 2; i++) {
            int idx = tid + i * 256;
            int r = idx >> 2, kq = (idx & 3) << 2;
            float4 v = *(const float4*)(A + (size_t)(m0 + r) * Kp + (k0 + kq));
            split_tf32(v.x, Ahi[kq + 0][r], Alo[kq + 0][r]);
            split_tf32(v.y, Ahi[kq + 1][r], Alo[kq + 1][r]);
            split_tf32(v.z, Ahi[kq + 2][r], Alo[kq + 2][r]);
            split_tf32(v.w, Ahi[kq + 3][r], Alo[kq + 3][r]);
        }
        // stage B tile 64x16
        {
            int r = tid >> 2, kq = (tid & 3) << 2;
            float4 v = *(const float4*)(B + (size_t)(n0 + r) * Kp + (k0 + kq));
            split_tf32(v.x, Bhi[r][kq + 0], Blo[r][kq + 0]);
            split_tf32(v.y, Bhi[r][kq + 1], Blo[r][kq + 1]);
            split_tf32(v.z, Bhi[r][kq + 2], Blo[r][kq + 2]);
            split_tf32(v.w, Bhi[r][kq + 3], Blo[r][kq + 3]);
        }
        __syncthreads();

#pragma unroll
        for (int ks = 0; ks < 16; ks += 8) {
            uint32_t ahi[2][4], alo[2][4], bhi[4][2], blo[4][2];
#pragma unroll
            for (int j = 0; j < 4; j++) {
                int nn = nw * 32 + j * 8 + g;
                bhi[j][0] = Bhi[nn][ks + t4];     blo[j][0] = Blo[nn][ks + t4];
                bhi[j][1] = Bhi[nn][ks + t4 + 4]; blo[j][1] = Blo[nn][ks + t4 + 4];
            }
#pragma unroll
            for (int i = 0; i < 2; i++) {
                int rr = mw * 32 + i * 16 + g;
                ahi[i][0] = Ahi[ks + t4][rr];          alo[i][0] = Alo[ks + t4][rr];
                ahi[i][1] = Ahi[ks + t4][rr + 8];      alo[i][1] = Alo[ks + t4][rr + 8];
                ahi[i][2] = Ahi[ks + t4 + 4][rr];      alo[i][2] = Alo[ks + t4 + 4][rr];
                ahi[i][3] = Ahi[ks + t4 + 4][rr + 8];  alo[i][3] = Alo[ks + t4 + 4][rr + 8];
            }
#pragma unroll
            for (int i = 0; i < 2; i++)
#pragma unroll
                for (int j = 0; j < 4; j++) {
                    mma_tf32(acc[i][j], ahi[i], bhi[j]);
                    mma_tf32(acc[i][j], alo[i], bhi[j]);
                    mma_tf32(acc[i][j], ahi[i], blo[j]);
                }
        }
        __syncthreads();
    }

    // epilogue: bias + relu
#pragma unroll
    for (int i = 0; i < 2; i++) {
#pragma unroll
        for (int j = 0; j < 4; j++) {
            int ncol = n0 + nw * 32 + j * 8 + 2 * t4;
            if (ncol >= Nout) continue;            // Nout multiple of 8: pair safe
            float b0 = bias[ncol], b1 = bias[ncol + 1];
            int mrow = m0 + mw * 32 + i * 16 + g;
            if (mrow < M) {
                float2 r0 = {fmaxf(acc[i][j][0] + b0, 0.f), fmaxf(acc[i][j][1] + b1, 0.f)};
                *(float2*)(C + (size_t)mrow * ldc + ncol) = r0;
            }
            if (mrow + 8 < M) {
                float2 r1 = {fmaxf(acc[i][j][2] + b0, 0.f), fmaxf(acc[i][j][3] + b1, 0.f)};
                *(float2*)(C + (size_t)(mrow + 8) * ldc + ncol) = r1;
            }
        }
    }
}

// ---------------- driver ----------------------------------------------------
extern "C" void kernel_launch(void* const* d_in, const int* in_sizes, int n_in,
                              void* d_out, int out_size) {
    const float* nf  = (const float*)d_in[0];
    const float* ef  = (const float*)d_in[1];
    const float* Wm1 = (const float*)d_in[2];  const float* bm1 = (const float*)d_in[3];
    const float* Wa1 = (const float*)d_in[4];  const float* ba1 = (const float*)d_in[5];
    const float* Wm2 = (const float*)d_in[6];  const float* bm2 = (const float*)d_in[7];
    const float* Wa2 = (const float*)d_in[8];  const float* ba2 = (const float*)d_in[9];
    const float* Wm3 = (const float*)d_in[10]; const float* bm3 = (const float*)d_in[11];
    const float* Wa3 = (const float*)d_in[12]; const float* ba3 = (const float*)d_in[13];
    const int* src = (const int*)d_in[14];
    const int* dst = (const int*)d_in[15];
    float* out = (float*)d_out;

    float *p_h1, *p_h2, *p_xc1, *p_xc2, *p_wc1, *p_wc2, *p_wc3;
    int *p_cnt, *p_fill;
    cudaGetSymbolAddress((void**)&p_cnt,  g_cnt);
    cudaGetSymbolAddress((void**)&p_fill, g_fill);
    cudaGetSymbolAddress((void**)&p_h1,   g_h1);
    cudaGetSymbolAddress((void**)&p_h2,   g_h2);
    cudaGetSymbolAddress((void**)&p_xc1,  g_xc1);
    cudaGetSymbolAddress((void**)&p_xc2,  g_xc2);
    cudaGetSymbolAddress((void**)&p_wc1,  g_wc1);
    cudaGetSymbolAddress((void**)&p_wc2,  g_wc2);
    cudaGetSymbolAddress((void**)&p_wc3,  g_wc3);

    const int GW = (NN * 32 + 255) / 256;   // warp-per-node grids

    // ---- CSR build (int atomics only; ~2.4M ops) ----
    k_zero_i<<<(NP + 255) / 256, 256>>>(p_cnt, NP);
    k_zero_i<<<(NP + 255) / 256, 256>>>(p_fill, NP);
    k_count<<<(NE + 255) / 256, 256>>>(dst);
    k_scan1<<<NB, 512>>>();
    k_scan2<<<1, 32>>>();
    k_scan3<<<(NP + 255) / 256, 256>>>();
    k_fill<<<(NE + 255) / 256, 256>>>(src, dst);

    // ---- graph-constant: edge-feature aggregation + static Xc columns ----
    k_gather_e<<<GW, 256>>>(ef);
    k_static<208,  64><<<(NP * 208 + 255) / 256, 256>>>(p_xc1);
    k_static<384, 152><<<(NP * 384 + 255) / 256, 256>>>(p_xc2);

    // ---- fused weights ----
    k_zero_f<<<(192 * 208 + 255) / 256, 256>>>(p_wc1, 192 * 208);
    k_zero_f<<<(192 * 384 + 255) / 256, 256>>>(p_wc2, 192 * 384);
    k_zero_f<<<(64 * 384 + 255) / 256, 256>>>(p_wc3, 64 * 384);
    k_wc<<<dim3(2, 152), 128>>>(Wm1, bm1, Wa1, p_wc1, 64, 152, 152, 208);
    k_wc<<<dim3(3, 152), 128>>>(Wm2, bm2, Wa2, p_wc2, 152, 152, 152, 384);
    k_wc<<<dim3(3, 64), 128>>>(Wm3, bm3, Wa3, p_wc3, 152, 64, 64, 384);

    // ---- layer 1 (64 -> 152) ----
    k_gather<16, 64, 208><<<GW, 256>>>(nf, 64, p_xc1);
    k_gemm_tc<<<dim3(NP / 128, 3), 256>>>(p_xc1, p_wc1, ba1, p_h1, NN, 152, 208, HID);

    // ---- layer 2 (152 -> 152) ----
    k_gather<38, 152, 384><<<GW, 256>>>(p_h1, HID, p_xc2);
    k_gemm_tc<<<dim3(NP / 128, 3), 256>>>(p_xc2, p_wc2, ba2, p_h2, NN, 152, 384, HID);

    // ---- layer 3 (152 -> 64) ----
    k_gather<38, 152, 384><<<GW, 256>>>(p_h2, HID, p_xc2);
    k_gemm_tc<<<dim3(NP / 128, 1), 256>>>(p_xc2, p_wc3, ba3, out, NN, 64, 384, 64);
}

// round 11
// speedup vs baseline: 1.3414x; 1.3414x over previous
#include <cuda_runtime.h>
#include <cstdint>

#define NN 50000      // nodes
#define NE 800000     // edges
#define NP 50048      // nodes padded to multiple of 128
#define NB 98         // scan blocks: ceil(NP/512)
#define ED 64         // edge feature dim
#define HID 152

// ---------------- scratch (device globals; no allocation allowed) ----------
__device__ int   g_cnt[NP];
__device__ int   g_fill[NP];
__device__ int   g_base[NP + 1];
__device__ int   g_bsum[128];
__device__ int   g_src[NE];      // src node per edge, CSR-ordered by dst
__device__ int   g_eid[NE];      // original edge id, CSR-ordered by dst
__device__ float g_eagg[(size_t)NP * ED];
__device__ float g_h1[(size_t)NP * HID];
__device__ float g_h2[(size_t)NP * HID];
__device__ float g_xc1[(size_t)NP * 208];
__device__ float g_xc2[(size_t)NP * 384];
__device__ float g_wc1[192 * 208];
__device__ float g_wc2[192 * 384];
__device__ float g_wc3[64 * 384];

// ---------------- utility ---------------------------------------------------
__global__ void k_zero_f(float* __restrict__ p, int n) {
    int t = blockIdx.x * blockDim.x + threadIdx.x;
    if (t < n) p[t] = 0.f;
}
__global__ void k_zero_i(int* __restrict__ p, int n) {
    int t = blockIdx.x * blockDim.x + threadIdx.x;
    if (t < n) p[t] = 0;
}

// ---------------- CSR build -------------------------------------------------
__global__ void k_count(const int* __restrict__ dst) {
    int t = blockIdx.x * blockDim.x + threadIdx.x;
    if (t < NE) atomicAdd(&g_cnt[dst[t]], 1);
}

__global__ void k_scan1() {
    __shared__ int sh[512];
    int b = blockIdx.x, t = threadIdx.x, i = b * 512 + t;
    int v = (i < NP) ? g_cnt[i] : 0;
    sh[t] = v;
    __syncthreads();
#pragma unroll
    for (int o = 1; o < 512; o <<= 1) {
        int x = (t >= o) ? sh[t - o] : 0;
        __syncthreads();
        sh[t] += x;
        __syncthreads();
    }
    if (i < NP) g_base[i + 1] = sh[t];
    if (t == 511) g_bsum[b] = sh[511];
}

__global__ void k_scan2() {
    if (threadIdx.x == 0) {
        int s = 0;
        for (int b = 0; b < NB; b++) { int c = g_bsum[b]; g_bsum[b] = s; s += c; }
    }
}

__global__ void k_scan3() {
    int i = blockIdx.x * blockDim.x + threadIdx.x;
    if (i < NP) g_base[i + 1] += g_bsum[i >> 9];
    if (i == 0) g_base[0] = 0;
}

__global__ void k_fill(const int* __restrict__ src, const int* __restrict__ dst) {
    int t = blockIdx.x * blockDim.x + threadIdx.x;
    if (t >= NE) return;
    int d = dst[t];
    int p = g_base[d] + atomicAdd(&g_fill[d], 1);
    g_src[p] = src[t];
    g_eid[p] = t;
}

// ---------------- edge-feature gather-sum per dst node ----------------------
__global__ void k_gather_e(const float* __restrict__ ef) {
    int w = (blockIdx.x * blockDim.x + threadIdx.x) >> 5;
    int lane = threadIdx.x & 31;
    if (w >= NN || lane >= 16) return;
    int e0 = g_base[w], e1 = g_base[w + 1];
    float4 a = {0.f, 0.f, 0.f, 0.f};
    for (int e = e0; e < e1; e++) {
        int id = g_eid[e];
        float4 v = *(const float4*)(ef + (size_t)id * ED + lane * 4);
        a.x += v.x; a.y += v.y; a.z += v.z; a.w += v.w;
    }
    *(float4*)(g_eagg + (size_t)w * ED + lane * 4) = a;
}

// ---------------- static columns of fused GEMM input (once per launch) ------
// layout per row v: [0,FIN)=x  [FIN,2FIN)=inv*na  [2FIN,2FIN+64)=inv*eagg
//                   [2FIN+64]=indicator  rest=0 ; pad rows fully 0
template <int KP, int FIN>
__global__ void k_static(float* __restrict__ XC) {
    int t = blockIdx.x * blockDim.x + threadIdx.x;
    if (t >= NP * KP) return;
    int v = t / KP, col = t - v * KP;
    float* p = XC + (size_t)v * KP + col;
    if (v >= NN) { *p = 0.f; return; }
    if (col < 2 * FIN) return;                 // dynamic: written by gather each layer
    int dg = g_cnt[v];
    float val = 0.f;
    if (col < 2 * FIN + 64) {
        float inv = 1.f / (float)max(dg, 1);
        val = inv * g_eagg[(size_t)v * ED + (col - 2 * FIN)];
    } else if (col == 2 * FIN + 64) {
        val = (dg > 0) ? 1.f : 0.f;
    }
    *p = val;
}

// ---------------- per-layer: copy x + gather mean of src rows into XC -------
template <int NC4, int FIN, int KP>
__global__ void k_gather(const float* __restrict__ X, int ldx, float* __restrict__ XC) {
    int w = (blockIdx.x * blockDim.x + threadIdx.x) >> 5;
    int lane = threadIdx.x & 31;
    if (w >= NN) return;
    int e0 = g_base[w], e1 = g_base[w + 1];
    int c0 = lane, c1 = lane + 32;
    float4 a0 = {0.f, 0.f, 0.f, 0.f};
    float4 a1 = {0.f, 0.f, 0.f, 0.f};
    for (int e = e0; e < e1; e++) {
        int s = g_src[e];
        const float4* row = (const float4*)(X + (size_t)s * ldx);
        if (c0 < NC4) {
            float4 v = row[c0];
            a0.x += v.x; a0.y += v.y; a0.z += v.z; a0.w += v.w;
        }
        if (NC4 > 32 && c1 < NC4) {
            float4 v = row[c1];
            a1.x += v.x; a1.y += v.y; a1.z += v.z; a1.w += v.w;
        }
    }
    float inv = 1.f / fmaxf((float)(e1 - e0), 1.f);
    float4* out = (float4*)(XC + (size_t)w * KP);
    const float4* xrow = (const float4*)(X + (size_t)w * ldx);
    if (c0 < NC4) {
        out[c0] = xrow[c0];
        float4 r; r.x = a0.x * inv; r.y = a0.y * inv; r.z = a0.z * inv; r.w = a0.w * inv;
        out[FIN / 4 + c0] = r;
    }
    if (NC4 > 32 && c1 < NC4) {
        out[c1] = xrow[c1];
        float4 r; r.x = a1.x * inv; r.y = a1.y * inv; r.z = a1.z * inv; r.w = a1.w * inv;
        out[FIN / 4 + c1] = r;
    }
}

// ---------------- build fused weight Wc = [Wa_self | Wa_h@Wm_n | Wa_h@Wm_e | Wa_h@bm]
__global__ void k_wc(const float* __restrict__ Wm, const float* __restrict__ bm,
                     const float* __restrict__ Wa, float* __restrict__ Wc,
                     int Fin, int Fm, int Fout, int Kp) {
    int col = blockIdx.x * blockDim.x + threadIdx.x;
    int j = blockIdx.y;
    int K1 = 2 * Fin + ED + 1;
    if (col >= K1 || j >= Fout) return;
    int WmK = Fin + ED;
    int WaK = Fin + Fm;
    const float* wah = Wa + (size_t)j * WaK + Fin;
    float val;
    if (col < Fin) {
        val = Wa[(size_t)j * WaK + col];
    } else if (col < 2 * Fin) {
        int i = col - Fin;
        float s = 0.f;
        for (int t = 0; t < Fm; t++) s += wah[t] * Wm[(size_t)t * WmK + i];
        val = s;
    } else if (col < 2 * Fin + ED) {
        int i = col - 2 * Fin;
        float s = 0.f;
        for (int t = 0; t < Fm; t++) s += wah[t] * Wm[(size_t)t * WmK + Fin + i];
        val = s;
    } else {
        float s = 0.f;
        for (int t = 0; t < Fm; t++) s += wah[t] * bm[t];
        val = s;
    }
    Wc[(size_t)j * Kp + col] = val;
}

// ---------------- bf16x3 tensor-core GEMM: C = relu(Xc @ Wc^T + bias) -------
// BM=128, BN=64, BK=16; 256 threads = 8 warps in 4(m) x 2(n); warp tile 32x32.
// A/B split to bf16 hi+lo pairs AT STAGING, packed as bf16x2 (= mma fragment
// format). Inner loop: pure LDS.32 + mma.m16n8k16 (3-term: hh + lh + hl).

// pack two floats into bf16x2: low 16 = f_even(k), high 16 = f_odd(k+1)
__device__ __forceinline__ uint32_t pack_bf16x2(float f_even, float f_odd) {
    uint32_t r;
    asm("cvt.rn.satfinite.bf16x2.f32 %0, %1, %2;" : "=r"(r) : "f"(f_odd), "f"(f_even));
    return r;
}

// split pair (fe,fo) into hi bf16x2 and lo bf16x2 (residuals)
__device__ __forceinline__ void split_pair(float fe, float fo, uint32_t& hi, uint32_t& lo) {
    hi = pack_bf16x2(fe, fo);
    float he = __uint_as_float(hi << 16);
    float ho = __uint_as_float(hi & 0xFFFF0000u);
    lo = pack_bf16x2(fe - he, fo - ho);
}

__device__ __forceinline__ void mma_bf16(float* c, const uint32_t* a, const uint32_t* b) {
    asm volatile(
        "mma.sync.aligned.m16n8k16.row.col.f32.bf16.bf16.f32 "
        "{%0,%1,%2,%3}, {%4,%5,%6,%7}, {%8,%9}, {%0,%1,%2,%3};"
        : "+f"(c[0]), "+f"(c[1]), "+f"(c[2]), "+f"(c[3])
        : "r"(a[0]), "r"(a[1]), "r"(a[2]), "r"(a[3]), "r"(b[0]), "r"(b[1]));
}

__global__ __launch_bounds__(256) void k_gemm_bf(
    const float* __restrict__ A, const float* __restrict__ B,
    const float* __restrict__ bias, float* __restrict__ C,
    int M, int Nout, int Kp, int ldc) {
    // [kpair][m] / [n][kpair]; strides chosen conflict-free for fragment loads:
    // A: bank = (136*t4 + g) mod 32 = 8*t4+g bijective over 32 lanes
    // B: bank = (12*g + t4) mod 32 all-distinct
    __shared__ uint32_t Ahi[8][136], Alo[8][136];
    __shared__ uint32_t Bhi[64][12], Blo[64][12];
    const int m0 = blockIdx.x * 128;
    const int n0 = blockIdx.y * 64;
    const int tid = threadIdx.x;
    const int lane = tid & 31, wid = tid >> 5;
    const int mw = wid >> 1, nw = wid & 1;     // 4 x 2 warp grid
    const int g = lane >> 2, t4 = lane & 3;

    float acc[2][4][4];
#pragma unroll
    for (int i = 0; i < 2; i++)
#pragma unroll
        for (int j = 0; j < 4; j++)
#pragma unroll
            for (int e = 0; e < 4; e++) acc[i][j][e] = 0.f;

    for (int k0 = 0; k0 < Kp; k0 += 16) {
        // stage A tile 128x16: thread handles rows idx>>2, k-quad (idx&3)*4
#pragma unroll
        for (int i = 0; i < 2; i++) {
            int idx = tid + i * 256;
            int r = idx >> 2, kq = (idx & 3) << 2, kp = (idx & 3) << 1;
            float4 v = *(const float4*)(A + (size_t)(m0 + r) * Kp + (k0 + kq));
            split_pair(v.x, v.y, Ahi[kp][r],     Alo[kp][r]);
            split_pair(v.z, v.w, Ahi[kp + 1][r], Alo[kp + 1][r]);
        }
        // stage B tile 64x16
        {
            int r = tid >> 2, kq = (tid & 3) << 2, kp = (tid & 3) << 1;
            float4 v = *(const float4*)(B + (size_t)(n0 + r) * Kp + (k0 + kq));
            split_pair(v.x, v.y, Bhi[r][kp],     Blo[r][kp]);
            split_pair(v.z, v.w, Bhi[r][kp + 1], Blo[r][kp + 1]);
        }
        __syncthreads();

        // one m16n8k16 K-step covers the whole 16-wide tile
        uint32_t ah[2][4], al[2][4], bh[4][2], bl[4][2];
#pragma unroll
        for (int j = 0; j < 4; j++) {
            int nn = nw * 32 + j * 8 + g;
            bh[j][0] = Bhi[nn][t4];     bl[j][0] = Blo[nn][t4];
            bh[j][1] = Bhi[nn][t4 + 4]; bl[j][1] = Blo[nn][t4 + 4];
        }
#pragma unroll
        for (int i = 0; i < 2; i++) {
            int rr = mw * 32 + i * 16 + g;
            ah[i][0] = Ahi[t4][rr];     al[i][0] = Alo[t4][rr];
            ah[i][1] = Ahi[t4][rr + 8]; al[i][1] = Alo[t4][rr + 8];
            ah[i][2] = Ahi[t4 + 4][rr];     al[i][2] = Alo[t4 + 4][rr];
            ah[i][3] = Ahi[t4 + 4][rr + 8]; al[i][3] = Alo[t4 + 4][rr + 8];
        }
#pragma unroll
        for (int i = 0; i < 2; i++)
#pragma unroll
            for (int j = 0; j < 4; j++) {
                mma_bf16(acc[i][j], ah[i], bh[j]);
                mma_bf16(acc[i][j], al[i], bh[j]);
                mma_bf16(acc[i][j], ah[i], bl[j]);
            }
        __syncthreads();
    }

    // epilogue: bias + relu (c0,c1 = row g cols 2t4..+1; c2,c3 = row g+8)
#pragma unroll
    for (int i = 0; i < 2; i++) {
#pragma unroll
        for (int j = 0; j < 4; j++) {
            int ncol = n0 + nw * 32 + j * 8 + 2 * t4;
            if (ncol >= Nout) continue;            // Nout multiple of 8: pair safe
            float b0 = bias[ncol], b1 = bias[ncol + 1];
            int mrow = m0 + mw * 32 + i * 16 + g;
            if (mrow < M) {
                float2 r0 = {fmaxf(acc[i][j][0] + b0, 0.f), fmaxf(acc[i][j][1] + b1, 0.f)};
                *(float2*)(C + (size_t)mrow * ldc + ncol) = r0;
            }
            if (mrow + 8 < M) {
                float2 r1 = {fmaxf(acc[i][j][2] + b0, 0.f), fmaxf(acc[i][j][3] + b1, 0.f)};
                *(float2*)(C + (size_t)(mrow + 8) * ldc + ncol) = r1;
            }
        }
    }
}

// ---------------- driver ----------------------------------------------------
extern "C" void kernel_launch(void* const* d_in, const int* in_sizes, int n_in,
                              void* d_out, int out_size) {
    const float* nf  = (const float*)d_in[0];
    const float* ef  = (const float*)d_in[1];
    const float* Wm1 = (const float*)d_in[2];  const float* bm1 = (const float*)d_in[3];
    const float* Wa1 = (const float*)d_in[4];  const float* ba1 = (const float*)d_in[5];
    const float* Wm2 = (const float*)d_in[6];  const float* bm2 = (const float*)d_in[7];
    const float* Wa2 = (const float*)d_in[8];  const float* ba2 = (const float*)d_in[9];
    const float* Wm3 = (const float*)d_in[10]; const float* bm3 = (const float*)d_in[11];
    const float* Wa3 = (const float*)d_in[12]; const float* ba3 = (const float*)d_in[13];
    const int* src = (const int*)d_in[14];
    const int* dst = (const int*)d_in[15];
    float* out = (float*)d_out;

    float *p_h1, *p_h2, *p_xc1, *p_xc2, *p_wc1, *p_wc2, *p_wc3;
    int *p_cnt, *p_fill;
    cudaGetSymbolAddress((void**)&p_cnt,  g_cnt);
    cudaGetSymbolAddress((void**)&p_fill, g_fill);
    cudaGetSymbolAddress((void**)&p_h1,   g_h1);
    cudaGetSymbolAddress((void**)&p_h2,   g_h2);
    cudaGetSymbolAddress((void**)&p_xc1,  g_xc1);
    cudaGetSymbolAddress((void**)&p_xc2,  g_xc2);
    cudaGetSymbolAddress((void**)&p_wc1,  g_wc1);
    cudaGetSymbolAddress((void**)&p_wc2,  g_wc2);
    cudaGetSymbolAddress((void**)&p_wc3,  g_wc3);

    const int GW = (NN * 32 + 255) / 256;   // warp-per-node grids

    // ---- CSR build (int atomics only; ~2.4M ops) ----
    k_zero_i<<<(NP + 255) / 256, 256>>>(p_cnt, NP);
    k_zero_i<<<(NP + 255) / 256, 256>>>(p_fill, NP);
    k_count<<<(NE + 255) / 256, 256>>>(dst);
    k_scan1<<<NB, 512>>>();
    k_scan2<<<1, 32>>>();
    k_scan3<<<(NP + 255) / 256, 256>>>();
    k_fill<<<(NE + 255) / 256, 256>>>(src, dst);

    // ---- graph-constant: edge-feature aggregation + static Xc columns ----
    k_gather_e<<<GW, 256>>>(ef);
    k_static<208,  64><<<(NP * 208 + 255) / 256, 256>>>(p_xc1);
    k_static<384, 152><<<(NP * 384 + 255) / 256, 256>>>(p_xc2);

    // ---- fused weights ----
    k_zero_f<<<(192 * 208 + 255) / 256, 256>>>(p_wc1, 192 * 208);
    k_zero_f<<<(192 * 384 + 255) / 256, 256>>>(p_wc2, 192 * 384);
    k_zero_f<<<(64 * 384 + 255) / 256, 256>>>(p_wc3, 64 * 384);
    k_wc<<<dim3(2, 152), 128>>>(Wm1, bm1, Wa1, p_wc1, 64, 152, 152, 208);
    k_wc<<<dim3(3, 152), 128>>>(Wm2, bm2, Wa2, p_wc2, 152, 152, 152, 384);
    k_wc<<<dim3(3, 64), 128>>>(Wm3, bm3, Wa3, p_wc3, 152, 64, 64, 384);

    // ---- layer 1 (64 -> 152) ----
    k_gather<16, 64, 208><<<GW, 256>>>(nf, 64, p_xc1);
    k_gemm_bf<<<dim3(NP / 128, 3), 256>>>(p_xc1, p_wc1, ba1, p_h1, NN, 152, 208, HID);

    // ---- layer 2 (152 -> 152) ----
    k_gather<38, 152, 384><<<GW, 256>>>(p_h1, HID, p_xc2);
    k_gemm_bf<<<dim3(NP / 128, 3), 256>>>(p_xc2, p_wc2, ba2, p_h2, NN, 152, 384, HID);

    // ---- layer 3 (152 -> 64) ----
    k_gather<38, 152, 384><<<GW, 256>>>(p_h2, HID, p_xc2);
    k_gemm_bf<<<dim3(NP / 128, 1), 256>>>(p_xc2, p_wc3, ba3, out, NN, 64, 384, 64);
}